// round 7
// baseline (speedup 1.0000x reference)
#include <cuda_runtime.h>
#include <cuda_fp16.h>
#include <cstdint>

namespace {
constexpr int kF       = 50;
constexpr int kE       = 64;
constexpr int kD       = 128;
constexpr int kIters   = 8;                  // b's per CTA
constexpr int kGrid    = 16384 / kIters;     // 2048 CTAs
constexpr int kThreads = 256;
constexpr uint32_t kBufB = 8192;             // X tile: 64 e-rows x 128B (64 fp16 f)
}

__device__ __forceinline__ uint32_t smem_u32(const void* p) {
    uint32_t a;
    asm("{ .reg .u64 t; cvta.to.shared.u64 t, %1; cvt.u32.u64 %0, t; }"
        : "=r"(a) : "l"(p));
    return a;
}

__device__ __forceinline__ uint32_t packh2(float lo, float hi) {
    __half2 h = __floats2half2_rn(lo, hi);
    return *reinterpret_cast<uint32_t*>(&h);
}

__device__ __forceinline__ void ldsm4(uint32_t& r0, uint32_t& r1, uint32_t& r2,
                                      uint32_t& r3, uint32_t a) {
    asm volatile("ldmatrix.sync.aligned.m8n8.x4.shared.b16 {%0,%1,%2,%3}, [%4];"
                 : "=r"(r0), "=r"(r1), "=r"(r2), "=r"(r3) : "r"(a));
}

__device__ __forceinline__ void mma16816(float d[4], const uint32_t a[4],
                                         uint32_t b0, uint32_t b1) {
    asm volatile(
        "mma.sync.aligned.m16n8k16.row.col.f32.f16.f16.f32 "
        "{%0,%1,%2,%3}, {%4,%5,%6,%7}, {%8,%9}, {%0,%1,%2,%3};"
        : "+f"(d[0]), "+f"(d[1]), "+f"(d[2]), "+f"(d[3])
        : "r"(a[0]), "r"(a[1]), "r"(a[2]), "r"(a[3]), "r"(b0), "r"(b1));
}

__global__ void __launch_bounds__(kThreads, 2)
InnerProduct_f16_kernel(const float* __restrict__ X,
                        const float* __restrict__ Th,
                        float* __restrict__ out) {
    __shared__ __align__(16) char xs[2 * kBufB];   // 2-stage X double buffer
    __shared__ float scratch[2][2][kD];            // [parity][ehalf][d]

    const int tid  = threadIdx.x;
    const int lane = tid & 31;
    const int warp = tid >> 5;
    const int g    = lane >> 2;       // 0..7
    const int q    = lane & 3;        // 0..3
    const int dbase = (warp & 3) << 5;   // 32 d-rows per warp
    const int ehalf = warp >> 2;         // 0/1: e-range [ehalf*32, +32)

    // ---- Build Theta A-fragments (fp16) in registers, once.
    // m16n8k16 A frag: a0:(row g, f 16s+2q,+1) a1:(row g+8, same f)
    //                  a2:(row g, f 16s+2q+8,+1) a3:(row g+8, same f)
    // K padded 50 -> 64 with zeros (pad products are exactly 0).
    uint32_t af[2][4][4];
#pragma unroll
    for (int t = 0; t < 2; ++t)
#pragma unroll
        for (int s = 0; s < 4; ++s) {
            const int r0 = dbase + 16 * t + g;
            const int r1 = r0 + 8;
            const int f0 = 16 * s + 2 * q;
            const int f1 = f0 + 8;
            auto thv = [&](int d, int f) -> float {
                return (f < kF) ? Th[d * kF + f] : 0.f;
            };
            af[t][s][0] = packh2(thv(r0, f0), thv(r0, f0 + 1));
            af[t][s][1] = packh2(thv(r1, f0), thv(r1, f0 + 1));
            af[t][s][2] = packh2(thv(r0, f1), thv(r0, f1 + 1));
            af[t][s][3] = packh2(thv(r1, f1), thv(r1, f1 + 1));
        }

    const uint32_t sb = smem_u32(xs);
    const size_t bstart = (size_t)blockIdx.x * kIters;

    // ---- Loader, two halves with a full iteration between them:
    //   ldg_tile: issue 16 coalesced LDG.32 into registers (raw fp32; NO
    //             dependent op afterwards -> latency hidden by the pipeline)
    //   sts_tile: one iteration later, cvt+pack+swizzled STS.128
    // Tile layout: [e=64 rows][f=64 fp16] (zero-padded 50->64), SW128 swizzle.
    float v[2][16];  // raw fp32 for 2 tiles in flight

    auto ldg_tile = [&](int b, float* dst) {
        const float* src = X + (bstart + b) * (size_t)(kF * kE);
#pragma unroll
        for (int i = 0; i < 2; ++i) {
            const int task = tid + kThreads * i;
            const int e  = task & 63;
            const int kb = task >> 6;          // 16B block: f = 8*kb .. +7
#pragma unroll
            for (int j = 0; j < 8; ++j) {
                const int fj = kb * 8 + j;
                dst[i * 8 + j] = (fj < kF) ? src[fj * kE + e] : 0.f;
            }
        }
    };
    auto sts_tile = [&](int stage, const float* vv) {
        const uint32_t base = sb + (uint32_t)stage * kBufB;
#pragma unroll
        for (int i = 0; i < 2; ++i) {
            const int task = tid + kThreads * i;
            const uint32_t e  = (uint32_t)(task & 63);
            const uint32_t kb = (uint32_t)(task >> 6);
            const uint32_t off = e * 128u + ((kb ^ (e & 7u)) << 4);
            const uint32_t p0 = packh2(vv[i * 8 + 0], vv[i * 8 + 1]);
            const uint32_t p1 = packh2(vv[i * 8 + 2], vv[i * 8 + 3]);
            const uint32_t p2 = packh2(vv[i * 8 + 4], vv[i * 8 + 5]);
            const uint32_t p3 = packh2(vv[i * 8 + 6], vv[i * 8 + 7]);
            asm volatile("st.shared.v4.b32 [%0], {%1,%2,%3,%4};"
                         :: "r"(base + off), "r"(p0), "r"(p1), "r"(p2), "r"(p3)
                         : "memory");
        }
    };

    // ldmatrix lane geometry: m = lane/8 selects {ntile-lo,k-lo | lo,k-hi |
    // hi,k-lo | hi,k-hi}; r = lane%8 is the e-row within the 8x8 matrix.
    const int m   = lane >> 3;
    const int r8  = lane & 7;
    const int klo = m & 1;
    const int eL0 = ehalf * 32 + ((m >> 1) << 3) + r8;  // p=0 base e-row

    // ---- Prologue: tile0 (exposed stall, once), tile1 LDG in flight ----
    ldg_tile(0, v[0]);
    sts_tile(0, v[0]);
    ldg_tile(1, v[1]);
    __syncthreads();

#pragma unroll 1
    for (int it = 0; it < kIters; ++it) {
        const uint32_t base = sb + (uint32_t)(it & 1) * kBufB;

        float acc[2][4][4];
#pragma unroll
        for (int t = 0; t < 2; ++t)
#pragma unroll
            for (int n = 0; n < 4; ++n)
#pragma unroll
                for (int c = 0; c < 4; ++c) acc[t][n][c] = 0.f;

        // proj[d,e] = sum_f Theta[d,f] * X[f,e]
#pragma unroll
        for (int s = 0; s < 4; ++s) {
#pragma unroll
            for (int p = 0; p < 2; ++p) {
                const uint32_t e = (uint32_t)(eL0 + 16 * p);
                const uint32_t kb = (uint32_t)(2 * s + klo);
                uint32_t b0, b1, b2, b3;
                ldsm4(b0, b1, b2, b3, base + e * 128u + ((kb ^ (e & 7u)) << 4));
                mma16816(acc[0][2 * p + 0], af[0][s], b0, b1);
                mma16816(acc[1][2 * p + 0], af[1][s], b0, b1);
                mma16816(acc[0][2 * p + 1], af[0][s], b2, b3);
                mma16816(acc[1][2 * p + 1], af[1][s], b2, b3);
            }
        }

        // ---- Issue next tile's STS (loads arrived ~1 iter ago) and the
        // tile-after-next's LDGs (pure issue, no dependent consumer here).
        if (it + 1 < kIters) sts_tile((it + 1) & 1, v[(it + 1) & 1]);
        if (it + 2 < kIters) ldg_tile(it + 2, v[it & 1]);

        // ---- Epilogue: partial L_p over this warp's 32 e's, quad-reduced.
        // C frag: c0:(g, 2q) c1:(g, 2q+1) c2:(g+8, ..) c3.
        const int par = it & 1;
#pragma unroll
        for (int t = 0; t < 2; ++t) {
            float s0 = 0.f, s1 = 0.f;
#pragma unroll
            for (int n = 0; n < 4; ++n) {
                s0 = fmaf(acc[t][n][0], acc[t][n][0], s0);
                s0 = fmaf(acc[t][n][1], acc[t][n][1], s0);
                s1 = fmaf(acc[t][n][2], acc[t][n][2], s1);
                s1 = fmaf(acc[t][n][3], acc[t][n][3], s1);
            }
            s0 += __shfl_xor_sync(0xffffffffu, s0, 1);
            s0 += __shfl_xor_sync(0xffffffffu, s0, 2);
            s1 += __shfl_xor_sync(0xffffffffu, s1, 1);
            s1 += __shfl_xor_sync(0xffffffffu, s1, 2);
            if (q == 0) {
                scratch[par][ehalf][dbase + 16 * t + g]     = s0;
                scratch[par][ehalf][dbase + 16 * t + g + 8] = s1;
            }
        }
        __syncthreads();

        // ---- Combine e-halves and store (coalesced 128 floats per b) ----
        if (tid < kD)
            out[(bstart + it) * kD + tid] =
                scratch[par][0][tid] + scratch[par][1][tid];
    }
}

extern "C" void kernel_launch(void* const* d_in, const int* in_sizes, int n_in,
                              void* d_out, int out_size) {
    const float* X  = (const float*)d_in[0];   // inputs [16384, 50, 64] fp32
    const float* Th = (const float*)d_in[1];   // Theta  [128, 50] fp32
    float* out      = (float*)d_out;           // [16384, 128] fp32
    (void)in_sizes; (void)n_in; (void)out_size;

    InnerProduct_f16_kernel<<<kGrid, kThreads>>>(X, Th, out);
}

// round 9
// speedup vs baseline: 1.0100x; 1.0100x over previous
#include <cuda_runtime.h>
#include <cuda_fp16.h>
#include <cstdint>

namespace {
constexpr int kF       = 50;
constexpr int kE       = 64;
constexpr int kD       = 128;
constexpr int kPairs   = 8;                      // b-pairs per CTA (16 b)
constexpr int kGrid    = 16384 / (2 * kPairs);   // 1024 CTAs
constexpr int kThreads = 256;
constexpr uint32_t kBufB = 8192;   // one X tile: 64 e-rows x 128B (64 fp16 f)
}

__device__ __forceinline__ uint32_t smem_u32(const void* p) {
    uint32_t a;
    asm("{ .reg .u64 t; cvta.to.shared.u64 t, %1; cvt.u32.u64 %0, t; }"
        : "=r"(a) : "l"(p));
    return a;
}

__device__ __forceinline__ uint32_t packh2(float lo, float hi) {
    __half2 h = __floats2half2_rn(lo, hi);
    return *reinterpret_cast<uint32_t*>(&h);
}

__device__ __forceinline__ void ldsm4(uint32_t& r0, uint32_t& r1, uint32_t& r2,
                                      uint32_t& r3, uint32_t a) {
    asm volatile("ldmatrix.sync.aligned.m8n8.x4.shared.b16 {%0,%1,%2,%3}, [%4];"
                 : "=r"(r0), "=r"(r1), "=r"(r2), "=r"(r3) : "r"(a));
}

__device__ __forceinline__ void mma16816(float d[4], const uint32_t a[4],
                                         uint32_t b0, uint32_t b1) {
    asm volatile(
        "mma.sync.aligned.m16n8k16.row.col.f32.f16.f16.f32 "
        "{%0,%1,%2,%3}, {%4,%5,%6,%7}, {%8,%9}, {%0,%1,%2,%3};"
        : "+f"(d[0]), "+f"(d[1]), "+f"(d[2]), "+f"(d[3])
        : "r"(a[0]), "r"(a[1]), "r"(a[2]), "r"(a[3]), "r"(b0), "r"(b1));
}

__global__ void __launch_bounds__(kThreads, 1)
InnerProduct_f16_kernel(const float* __restrict__ X,
                        const float* __restrict__ Th,
                        float* __restrict__ out) {
    __shared__ __align__(16) char xs[2 * 2 * kBufB];  // [stage][slot] tiles
    __shared__ float scratch[2][2][2][kD];            // [parity][slot][ehalf][d]

    const int tid  = threadIdx.x;
    const int lane = tid & 31;
    const int warp = tid >> 5;
    const int g    = lane >> 2;          // 0..7
    const int q    = lane & 3;           // 0..3
    const int slot  = warp >> 2;         // which b of the pair (0/1)
    const int mhalf = (warp >> 1) & 1;   // d-range [mhalf*64, +64)
    const int ehalf = warp & 1;          // e-range [ehalf*32, +32)
    const int dbase = mhalf << 6;
    const int ebase = ehalf << 5;

    // ---- Build Theta A-fragments (fp16) in registers, once. 4 m-tiles.
    // m16n8k16 A frag: a0:(row g, f 16s+2q,+1) a1:(row g+8, same f)
    //                  a2:(row g, f 16s+2q+8,+1) a3:(row g+8, same f)
    // K padded 50 -> 64 with zeros (pad products are exactly 0).
    uint32_t af[4][4][4];
#pragma unroll
    for (int t = 0; t < 4; ++t)
#pragma unroll
        for (int s = 0; s < 4; ++s) {
            const int r0 = dbase + 16 * t + g;
            const int r1 = r0 + 8;
            const int f0 = 16 * s + 2 * q;
            const int f1 = f0 + 8;
            auto thv = [&](int d, int f) -> float {
                return (f < kF) ? Th[d * kF + f] : 0.f;
            };
            af[t][s][0] = packh2(thv(r0, f0), thv(r0, f0 + 1));
            af[t][s][1] = packh2(thv(r1, f0), thv(r1, f0 + 1));
            af[t][s][2] = packh2(thv(r0, f1), thv(r0, f1 + 1));
            af[t][s][3] = packh2(thv(r1, f1), thv(r1, f1 + 1));
        }

    const uint32_t sb = smem_u32(xs);
    const size_t bstart = (size_t)blockIdx.x * (2 * kPairs);

    // ---- Loader (R5-proven idiom: coalesced LDG gather + immediate pack).
    // Tile layout: [e=64 rows][f=64 fp16] (zero-padded 50->64), SW128 swizzle.
    uint32_t v[2][8];  // packed fp16 staging for the 2 tiles of one pair

    auto ldg_cvt = [&](int b, uint32_t* dst) {
        const float* src = X + (bstart + b) * (size_t)(kF * kE);
#pragma unroll
        for (int i = 0; i < 2; ++i) {
            const int task = tid + kThreads * i;
            const int e  = task & 63;
            const int kb = task >> 6;          // 16B block: f = 8*kb .. +7
            float f[8];
#pragma unroll
            for (int j = 0; j < 8; ++j) {
                const int fj = kb * 8 + j;
                f[j] = (fj < kF) ? src[fj * kE + e] : 0.f;
            }
            dst[i * 4 + 0] = packh2(f[0], f[1]);
            dst[i * 4 + 1] = packh2(f[2], f[3]);
            dst[i * 4 + 2] = packh2(f[4], f[5]);
            dst[i * 4 + 3] = packh2(f[6], f[7]);
        }
    };
    auto sts_pair = [&](int stage) {
#pragma unroll
        for (int s2 = 0; s2 < 2; ++s2) {
            const uint32_t base =
                sb + (uint32_t)stage * (2 * kBufB) + (uint32_t)s2 * kBufB;
#pragma unroll
            for (int i = 0; i < 2; ++i) {
                const int task = tid + kThreads * i;
                const uint32_t e  = (uint32_t)(task & 63);
                const uint32_t kb = (uint32_t)(task >> 6);
                const uint32_t off = e * 128u + ((kb ^ (e & 7u)) << 4);
                asm volatile("st.shared.v4.b32 [%0], {%1,%2,%3,%4};"
                             :: "r"(base + off), "r"(v[s2][i * 4 + 0]),
                                "r"(v[s2][i * 4 + 1]), "r"(v[s2][i * 4 + 2]),
                                "r"(v[s2][i * 4 + 3]) : "memory");
            }
        }
    };

    // ldmatrix lane geometry: m = lane/8 selects {ntile-lo,k-lo | lo,k-hi |
    // hi,k-lo | hi,k-hi}; r = lane%8 is the e-row within the 8x8 matrix.
    const int m   = lane >> 3;
    const int r8  = lane & 7;
    const int klo = m & 1;
    const int eL0 = ebase + ((m >> 1) << 3) + r8;  // p=0 base e-row

    // ---- Prologue: pair0 staged+stored, pair1 staged ----
    ldg_cvt(0, v[0]);
    ldg_cvt(1, v[1]);
    sts_pair(0);
    ldg_cvt(2, v[0]);
    ldg_cvt(3, v[1]);
    __syncthreads();

#pragma unroll 1
    for (int it = 0; it < kPairs; ++it) {
        const uint32_t base =
            sb + (uint32_t)(it & 1) * (2 * kBufB) + (uint32_t)slot * kBufB;

        float acc[4][4][4];
#pragma unroll
        for (int t = 0; t < 4; ++t)
#pragma unroll
            for (int n = 0; n < 4; ++n)
#pragma unroll
                for (int c = 0; c < 4; ++c) acc[t][n][c] = 0.f;

        // proj[d,e] = sum_f Theta[d,f] * X[f,e]; each ldmatrix.x4 feeds 8 MMAs.
#pragma unroll
        for (int s = 0; s < 4; ++s) {
#pragma unroll
            for (int p = 0; p < 2; ++p) {
                const uint32_t e = (uint32_t)(eL0 + 16 * p);
                const uint32_t kb = (uint32_t)(2 * s + klo);
                uint32_t b0, b1, b2, b3;
                ldsm4(b0, b1, b2, b3, base + e * 128u + ((kb ^ (e & 7u)) << 4));
#pragma unroll
                for (int t = 0; t < 4; ++t) {
                    mma16816(acc[t][2 * p + 0], af[t][s], b0, b1);
                    mma16816(acc[t][2 * p + 1], af[t][s], b2, b3);
                }
            }
        }

        // ---- Store next pair's tiles; prefetch pair after next ----
        if (it + 1 < kPairs) sts_pair((it + 1) & 1);
        if (it + 2 < kPairs) {
            ldg_cvt(2 * (it + 2), v[0]);
            ldg_cvt(2 * (it + 2) + 1, v[1]);
        }

        // ---- Epilogue: partial L_p over this warp's 32 e's, quad-reduced.
        // C frag: c0:(g, 2q) c1:(g, 2q+1) c2:(g+8, ..) c3.
        const int par = it & 1;
#pragma unroll
        for (int t = 0; t < 4; ++t) {
            float s0 = 0.f, s1 = 0.f;
#pragma unroll
            for (int n = 0; n < 4; ++n) {
                s0 = fmaf(acc[t][n][0], acc[t][n][0], s0);
                s0 = fmaf(acc[t][n][1], acc[t][n][1], s0);
                s1 = fmaf(acc[t][n][2], acc[t][n][2], s1);
                s1 = fmaf(acc[t][n][3], acc[t][n][3], s1);
            }
            s0 += __shfl_xor_sync(0xffffffffu, s0, 1);
            s0 += __shfl_xor_sync(0xffffffffu, s0, 2);
            s1 += __shfl_xor_sync(0xffffffffu, s1, 1);
            s1 += __shfl_xor_sync(0xffffffffu, s1, 2);
            if (q == 0) {
                scratch[par][slot][ehalf][dbase + 16 * t + g]     = s0;
                scratch[par][slot][ehalf][dbase + 16 * t + g + 8] = s1;
            }
        }
        __syncthreads();

        // ---- Combine e-halves, store 2 b's (coalesced 2x512B) ----
        const int d  = tid & 127;
        const int sl = tid >> 7;
        out[(bstart + 2 * it + sl) * kD + d] =
            scratch[par][sl][0][d] + scratch[par][sl][1][d];
    }
}

extern "C" void kernel_launch(void* const* d_in, const int* in_sizes, int n_in,
                              void* d_out, int out_size) {
    const float* X  = (const float*)d_in[0];   // inputs [16384, 50, 64] fp32
    const float* Th = (const float*)d_in[1];   // Theta  [128, 50] fp32
    float* out      = (float*)d_out;           // [16384, 128] fp32
    (void)in_sizes; (void)n_in; (void)out_size;

    InnerProduct_f16_kernel<<<kGrid, kThreads>>>(X, Th, out);
}

// round 10
// speedup vs baseline: 1.3171x; 1.3040x over previous
#include <cuda_runtime.h>
#include <cuda_fp16.h>
#include <cstdint>

namespace {
constexpr int kF       = 50;
constexpr int kE       = 64;
constexpr int kD       = 128;
constexpr int kIters   = 8;                  // b's per CTA
constexpr int kGrid    = 16384 / kIters;     // 2048 CTAs
constexpr int kThreads = 256;
constexpr uint32_t kBufB = 8192;   // X tile: 64 f-rows x 128B (64 fp16 e)
}

__device__ __forceinline__ uint32_t smem_u32(const void* p) {
    uint32_t a;
    asm("{ .reg .u64 t; cvta.to.shared.u64 t, %1; cvt.u32.u64 %0, t; }"
        : "=r"(a) : "l"(p));
    return a;
}

__device__ __forceinline__ uint32_t packh2(float lo, float hi) {
    __half2 h = __floats2half2_rn(lo, hi);
    return *reinterpret_cast<uint32_t*>(&h);
}

__device__ __forceinline__ void ldsm4t(uint32_t& r0, uint32_t& r1, uint32_t& r2,
                                       uint32_t& r3, uint32_t a) {
    asm volatile(
        "ldmatrix.sync.aligned.m8n8.x4.trans.shared.b16 {%0,%1,%2,%3}, [%4];"
        : "=r"(r0), "=r"(r1), "=r"(r2), "=r"(r3) : "r"(a));
}

__device__ __forceinline__ void mma16816(float d[4], const uint32_t a[4],
                                         uint32_t b0, uint32_t b1) {
    asm volatile(
        "mma.sync.aligned.m16n8k16.row.col.f32.f16.f16.f32 "
        "{%0,%1,%2,%3}, {%4,%5,%6,%7}, {%8,%9}, {%0,%1,%2,%3};"
        : "+f"(d[0]), "+f"(d[1]), "+f"(d[2]), "+f"(d[3])
        : "r"(a[0]), "r"(a[1]), "r"(a[2]), "r"(a[3]), "r"(b0), "r"(b1));
}

__global__ void __launch_bounds__(kThreads, 3)
InnerProduct_f16_kernel(const float* __restrict__ X,
                        const float* __restrict__ Th,
                        float* __restrict__ out) {
    __shared__ __align__(16) char xs[2 * kBufB];   // 2-stage X double buffer

    const int tid  = threadIdx.x;
    const int lane = tid & 31;
    const int warp = tid >> 5;
    const int g    = lane >> 2;       // 0..7
    const int q    = lane & 3;        // 0..3
    const int dbase = warp << 4;      // 16 d-rows per warp, full 64 e

    // ---- Theta A-fragments (fp16) in registers, once. 1 m-tile, 4 k-steps.
    // m16n8k16 A frag: a0:(row g, f 16s+2q,+1)  a1:(row g+8, same f)
    //                  a2:(row g, f 16s+2q+8,+1) a3:(row g+8, same f)
    // K padded 50 -> 64 with zeros (pad products are exactly 0).
    uint32_t af[4][4];
#pragma unroll
    for (int s = 0; s < 4; ++s) {
        const int r0 = dbase + g;
        const int r1 = r0 + 8;
        const int f0 = 16 * s + 2 * q;
        const int f1 = f0 + 8;
        auto thv = [&](int d, int f) -> float {
            return (f < kF) ? Th[d * kF + f] : 0.f;
        };
        af[s][0] = packh2(thv(r0, f0), thv(r0, f0 + 1));
        af[s][1] = packh2(thv(r1, f0), thv(r1, f0 + 1));
        af[s][2] = packh2(thv(r0, f1), thv(r0, f1 + 1));
        af[s][3] = packh2(thv(r1, f1), thv(r1, f1 + 1));
    }

    const uint32_t sb = smem_u32(xs);
    const size_t bstart = (size_t)blockIdx.x * kIters;

    // ---- Zero the f-padding rows (50..63) of both stages, once. The loader
    // only ever writes f < 50, so they stay zero.
    for (int i = tid; i < 2 * (64 - kF) * 32; i += kThreads) {
        const int st = i / ((64 - kF) * 32);
        const int r  = i % ((64 - kF) * 32);
        reinterpret_cast<uint32_t*>(xs + st * kBufB + kF * 128)[r] = 0;
    }

    // ---- Loader: tile stored VERBATIM as [f=64 rows][e=64 fp16 cols],
    // 128B rows, SW128 XOR swizzle on the 16B unit. Pure streaming:
    // task t (0..399): f = t>>3, eb = t&7 -> 2 coalesced LDG.128 (8 floats,
    // e = 8*eb..+7), pack 4 h2 (adjacent e!), 1 swizzled STS.128.
    uint32_t v[8];  // packed fp16 staging, one tile in flight

    auto ldg_cvt = [&](int b) {
        const float* src = X + (bstart + b) * (size_t)(kF * kE);
#pragma unroll
        for (int i = 0; i < 2; ++i) {
            const int t = tid + kThreads * i;
            if (t < 400) {
                const int f  = t >> 3;
                const int eb = t & 7;
                const float4 lo = *reinterpret_cast<const float4*>(
                    src + f * kE + eb * 8);
                const float4 hi = *reinterpret_cast<const float4*>(
                    src + f * kE + eb * 8 + 4);
                v[i * 4 + 0] = packh2(lo.x, lo.y);
                v[i * 4 + 1] = packh2(lo.z, lo.w);
                v[i * 4 + 2] = packh2(hi.x, hi.y);
                v[i * 4 + 3] = packh2(hi.z, hi.w);
            }
        }
    };
    auto sts_tile = [&](int stage) {
        const uint32_t base = sb + (uint32_t)stage * kBufB;
#pragma unroll
        for (int i = 0; i < 2; ++i) {
            const int t = tid + kThreads * i;
            if (t < 400) {
                const uint32_t f  = (uint32_t)(t >> 3);
                const uint32_t eb = (uint32_t)(t & 7);
                const uint32_t off = f * 128u + ((eb ^ (f & 7u)) << 4);
                asm volatile("st.shared.v4.b32 [%0], {%1,%2,%3,%4};"
                             :: "r"(base + off), "r"(v[i * 4 + 0]),
                                "r"(v[i * 4 + 1]), "r"(v[i * 4 + 2]),
                                "r"(v[i * 4 + 3]) : "memory");
            }
        }
    };

    // ---- ldmatrix.x4.trans lane geometry. Matrix j = lane/8, row r = lane%8:
    //   m0=(f-lo8, e-lo8)  m1=(f-hi8, e-lo8)  m2=(f-lo8, e-hi8)  m3=(f-hi8, e-hi8)
    // so (r0,r1) = (b0,b1) of n-tile e-lo, (r2,r3) = n-tile e-hi.
    // Lane address: f = 16s + (j&1)*8 + r, e-unit u = 2*nb + (j>>1),
    // swizzled off = f*128 + ((u ^ r) << 4)   [since f&7 == r].
    const int j   = lane >> 3;
    const int r8  = lane & 7;
    const uint32_t lrow = (uint32_t)(((j & 1) * 8 + r8) * 128);
    const uint32_t lu   = (uint32_t)(j >> 1);

    // ---- Prologue ----
    ldg_cvt(0);
    sts_tile(0);
    ldg_cvt(1);
    __syncthreads();

#pragma unroll 1
    for (int it = 0; it < kIters; ++it) {
        const uint32_t base = sb + (uint32_t)(it & 1) * kBufB;

        // Store next tile (data loaded last iter), prefetch tile after next.
        if (it + 1 < kIters) sts_tile((it + 1) & 1);
        if (it + 2 < kIters) ldg_cvt(it + 2);

        float acc[8][4];
#pragma unroll
        for (int n = 0; n < 8; ++n)
#pragma unroll
            for (int c = 0; c < 4; ++c) acc[n][c] = 0.f;

        // proj[d,e] = sum_f Theta[d,f] * X[f,e]
#pragma unroll
        for (int s = 0; s < 4; ++s) {
            const uint32_t abase = base + (uint32_t)(2048 * s) + lrow;
#pragma unroll
            for (int nb = 0; nb < 4; ++nb) {
                const uint32_t u = 2u * (uint32_t)nb + lu;
                uint32_t b0, b1, b2, b3;
                ldsm4t(b0, b1, b2, b3, abase + (((u ^ (uint32_t)r8)) << 4));
                mma16816(acc[2 * nb + 0], af[s], b0, b1);
                mma16816(acc[2 * nb + 1], af[s], b2, b3);
            }
        }

        // ---- Epilogue: L_p[b,d] = sum_e proj^2 over all 64 e, quad-reduced.
        // C frag: c0:(g, 2q) c1:(g, 2q+1) c2:(g+8, 2q) c3:(g+8, 2q+1).
        float s0 = 0.f, s1 = 0.f;
#pragma unroll
        for (int n = 0; n < 8; ++n) {
            s0 = fmaf(acc[n][0], acc[n][0], s0);
            s0 = fmaf(acc[n][1], acc[n][1], s0);
            s1 = fmaf(acc[n][2], acc[n][2], s1);
            s1 = fmaf(acc[n][3], acc[n][3], s1);
        }
        s0 += __shfl_xor_sync(0xffffffffu, s0, 1);
        s0 += __shfl_xor_sync(0xffffffffu, s0, 2);
        s1 += __shfl_xor_sync(0xffffffffu, s1, 1);
        s1 += __shfl_xor_sync(0xffffffffu, s1, 2);
        if (q == 0) {
            float* op = out + (bstart + it) * kD + dbase;
            op[g]     = s0;
            op[g + 8] = s1;
        }
        __syncthreads();
    }
}

extern "C" void kernel_launch(void* const* d_in, const int* in_sizes, int n_in,
                              void* d_out, int out_size) {
    const float* X  = (const float*)d_in[0];   // inputs [16384, 50, 64] fp32
    const float* Th = (const float*)d_in[1];   // Theta  [128, 50] fp32
    float* out      = (float*)d_out;           // [16384, 128] fp32
    (void)in_sizes; (void)n_in; (void)out_size;

    InnerProduct_f16_kernel<<<kGrid, kThreads>>>(X, Th, out);
}

// round 11
// speedup vs baseline: 1.3452x; 1.0213x over previous
#include <cuda_runtime.h>
#include <cuda_fp16.h>
#include <cstdint>

namespace {
constexpr int kF       = 50;
constexpr int kE       = 64;
constexpr int kD       = 128;
constexpr int kPairs   = 4;                      // b-pairs per CTA (8 b)
constexpr int kGrid    = 16384 / (2 * kPairs);   // 2048 CTAs
constexpr int kThreads = 256;
constexpr uint32_t kBufB = 8192;   // one X tile: 64 f-rows x 128B (64 fp16 e)
}

__device__ __forceinline__ uint32_t smem_u32(const void* p) {
    uint32_t a;
    asm("{ .reg .u64 t; cvta.to.shared.u64 t, %1; cvt.u32.u64 %0, t; }"
        : "=r"(a) : "l"(p));
    return a;
}

__device__ __forceinline__ uint32_t packh2(float lo, float hi) {
    __half2 h = __floats2half2_rn(lo, hi);
    return *reinterpret_cast<uint32_t*>(&h);
}

__device__ __forceinline__ void ldsm4t(uint32_t& r0, uint32_t& r1, uint32_t& r2,
                                       uint32_t& r3, uint32_t a) {
    asm volatile(
        "ldmatrix.sync.aligned.m8n8.x4.trans.shared.b16 {%0,%1,%2,%3}, [%4];"
        : "=r"(r0), "=r"(r1), "=r"(r2), "=r"(r3) : "r"(a));
}

__device__ __forceinline__ void mma16816(float d[4], const uint32_t a[4],
                                         uint32_t b0, uint32_t b1) {
    asm volatile(
        "mma.sync.aligned.m16n8k16.row.col.f32.f16.f16.f32 "
        "{%0,%1,%2,%3}, {%4,%5,%6,%7}, {%8,%9}, {%0,%1,%2,%3};"
        : "+f"(d[0]), "+f"(d[1]), "+f"(d[2]), "+f"(d[3])
        : "r"(a[0]), "r"(a[1]), "r"(a[2]), "r"(a[3]), "r"(b0), "r"(b1));
}

__global__ void __launch_bounds__(kThreads, 2)
InnerProduct_f16_kernel(const float* __restrict__ X,
                        const float* __restrict__ Th,
                        float* __restrict__ out) {
    __shared__ __align__(16) char xs[2 * 2 * kBufB];  // [stage][slot] tiles

    const int tid  = threadIdx.x;
    const int lane = tid & 31;
    const int warp = tid >> 5;
    const int g    = lane >> 2;          // 0..7
    const int q    = lane & 3;           // 0..3
    const int slot  = warp >> 2;         // which b of the pair (0/1)
    const int dbase = (warp & 3) << 5;   // 32 d-rows per warp, full 64 e

    // ---- Theta A-fragments (fp16) in registers, once. 2 m-tiles, 4 k-steps.
    // m16n8k16 A frag: a0:(row g, f 16s+2q,+1)  a1:(row g+8, same f)
    //                  a2:(row g, f 16s+2q+8,+1) a3:(row g+8, same f)
    // K padded 50 -> 64 with zeros (pad products are exactly 0).
    uint32_t af[2][4][4];
#pragma unroll
    for (int t = 0; t < 2; ++t)
#pragma unroll
        for (int s = 0; s < 4; ++s) {
            const int r0 = dbase + 16 * t + g;
            const int r1 = r0 + 8;
            const int f0 = 16 * s + 2 * q;
            const int f1 = f0 + 8;
            auto thv = [&](int d, int f) -> float {
                return (f < kF) ? Th[d * kF + f] : 0.f;
            };
            af[t][s][0] = packh2(thv(r0, f0), thv(r0, f0 + 1));
            af[t][s][1] = packh2(thv(r1, f0), thv(r1, f0 + 1));
            af[t][s][2] = packh2(thv(r0, f1), thv(r0, f1 + 1));
            af[t][s][3] = packh2(thv(r1, f1), thv(r1, f1 + 1));
        }

    const uint32_t sb = smem_u32(xs);
    const size_t bstart = (size_t)blockIdx.x * (2 * kPairs);

    // ---- Zero the f-padding rows (50..63) of all 4 buffers, once.
    // The loader only ever writes f < 50, so they stay zero.
    for (int i = tid; i < 4 * (64 - kF) * 32; i += kThreads) {
        const int buf = i / ((64 - kF) * 32);
        const int r   = i % ((64 - kF) * 32);
        reinterpret_cast<uint32_t*>(xs + buf * kBufB + kF * 128)[r] = 0;
    }

    // ---- Loader (R9-proven): tile stored VERBATIM as [f=64 rows][e=64 fp16],
    // 128B rows, SW128 XOR swizzle on the 16B unit. Task t (0..399):
    // f = t>>3, eb = t&7 -> 2 coalesced LDG.128, pack 4 h2 (adjacent e),
    // 1 swizzled STS.128.
    uint32_t v[2][8];  // packed staging for the 2 tiles of one pair

    auto ldg_cvt = [&](int b, uint32_t* dst) {
        const float* src = X + (bstart + b) * (size_t)(kF * kE);
#pragma unroll
        for (int i = 0; i < 2; ++i) {
            const int t = tid + kThreads * i;
            if (t < 400) {
                const int f  = t >> 3;
                const int eb = t & 7;
                const float4 lo = *reinterpret_cast<const float4*>(
                    src + f * kE + eb * 8);
                const float4 hi = *reinterpret_cast<const float4*>(
                    src + f * kE + eb * 8 + 4);
                dst[i * 4 + 0] = packh2(lo.x, lo.y);
                dst[i * 4 + 1] = packh2(lo.z, lo.w);
                dst[i * 4 + 2] = packh2(hi.x, hi.y);
                dst[i * 4 + 3] = packh2(hi.z, hi.w);
            }
        }
    };
    auto sts_pair = [&](int stage) {
#pragma unroll
        for (int s2 = 0; s2 < 2; ++s2) {
            const uint32_t base =
                sb + (uint32_t)stage * (2 * kBufB) + (uint32_t)s2 * kBufB;
#pragma unroll
            for (int i = 0; i < 2; ++i) {
                const int t = tid + kThreads * i;
                if (t < 400) {
                    const uint32_t f  = (uint32_t)(t >> 3);
                    const uint32_t eb = (uint32_t)(t & 7);
                    const uint32_t off = f * 128u + ((eb ^ (f & 7u)) << 4);
                    asm volatile("st.shared.v4.b32 [%0], {%1,%2,%3,%4};"
                                 :: "r"(base + off), "r"(v[s2][i * 4 + 0]),
                                    "r"(v[s2][i * 4 + 1]), "r"(v[s2][i * 4 + 2]),
                                    "r"(v[s2][i * 4 + 3]) : "memory");
                }
            }
        }
    };

    // ---- ldmatrix.x4.trans lane geometry (R9-proven). Matrix j = lane/8,
    // row r = lane%8:
    //   m0=(f-lo8, e-lo8) m1=(f-hi8, e-lo8) m2=(f-lo8, e-hi8) m3=(f-hi8, e-hi8)
    // Lane address: f = 16s + (j&1)*8 + r, e-unit u = 2*nb + (j>>1),
    // swizzled off = f*128 + ((u ^ r) << 4)   [since f&7 == r].
    const int j   = lane >> 3;
    const int r8  = lane & 7;
    const uint32_t lrow = (uint32_t)(((j & 1) * 8 + r8) * 128);
    const uint32_t lu   = (uint32_t)(j >> 1);

    // ---- Prologue: pair0 staged+stored, pair1 staged ----
    ldg_cvt(0, v[0]);
    ldg_cvt(1, v[1]);
    sts_pair(0);
    ldg_cvt(2, v[0]);
    ldg_cvt(3, v[1]);
    __syncthreads();

#pragma unroll 1
    for (int it = 0; it < kPairs; ++it) {
        const uint32_t base =
            sb + (uint32_t)(it & 1) * (2 * kBufB) + (uint32_t)slot * kBufB;

        // Store next pair (data loaded last iter), prefetch pair after next.
        if (it + 1 < kPairs) sts_pair((it + 1) & 1);
        if (it + 2 < kPairs) {
            ldg_cvt(2 * (it + 2), v[0]);
            ldg_cvt(2 * (it + 2) + 1, v[1]);
        }

        float acc[2][8][4];
#pragma unroll
        for (int t = 0; t < 2; ++t)
#pragma unroll
            for (int n = 0; n < 8; ++n)
#pragma unroll
                for (int c = 0; c < 4; ++c) acc[t][n][c] = 0.f;

        // proj[d,e] = sum_f Theta[d,f] * X[f,e]; each ldsm.x4 feeds 4 MMAs.
#pragma unroll
        for (int s = 0; s < 4; ++s) {
            const uint32_t abase = base + (uint32_t)(2048 * s) + lrow;
#pragma unroll
            for (int nb = 0; nb < 4; ++nb) {
                const uint32_t u = 2u * (uint32_t)nb + lu;
                uint32_t b0, b1, b2, b3;
                ldsm4t(b0, b1, b2, b3, abase + ((u ^ (uint32_t)r8) << 4));
#pragma unroll
                for (int t = 0; t < 2; ++t) {
                    mma16816(acc[t][2 * nb + 0], af[t][s], b0, b1);
                    mma16816(acc[t][2 * nb + 1], af[t][s], b2, b3);
                }
            }
        }

        // ---- Epilogue: L_p[b,d] = sum_e proj^2 over all 64 e, quad-reduced.
        // C frag: c0:(g, 2q) c1:(g, 2q+1) c2:(g+8, 2q) c3:(g+8, 2q+1).
        float* op = out + (bstart + 2 * it + slot) * kD + dbase;
#pragma unroll
        for (int t = 0; t < 2; ++t) {
            float s0 = 0.f, s1 = 0.f;
#pragma unroll
            for (int n = 0; n < 8; ++n) {
                s0 = fmaf(acc[t][n][0], acc[t][n][0], s0);
                s0 = fmaf(acc[t][n][1], acc[t][n][1], s0);
                s1 = fmaf(acc[t][n][2], acc[t][n][2], s1);
                s1 = fmaf(acc[t][n][3], acc[t][n][3], s1);
            }
            s0 += __shfl_xor_sync(0xffffffffu, s0, 1);
            s0 += __shfl_xor_sync(0xffffffffu, s0, 2);
            s1 += __shfl_xor_sync(0xffffffffu, s1, 1);
            s1 += __shfl_xor_sync(0xffffffffu, s1, 2);
            if (q == 0) {
                op[16 * t + g]     = s0;
                op[16 * t + g + 8] = s1;
            }
        }
        __syncthreads();
    }
}

extern "C" void kernel_launch(void* const* d_in, const int* in_sizes, int n_in,
                              void* d_out, int out_size) {
    const float* X  = (const float*)d_in[0];   // inputs [16384, 50, 64] fp32
    const float* Th = (const float*)d_in[1];   // Theta  [128, 50] fp32
    float* out      = (float*)d_out;           // [16384, 128] fp32
    (void)in_sizes; (void)n_in; (void)out_size;

    InnerProduct_f16_kernel<<<kGrid, kThreads>>>(X, Th, out);
}

// round 15
// speedup vs baseline: 1.5139x; 1.1254x over previous
#include <cuda_runtime.h>
#include <cuda_fp16.h>
#include <cstdint>

namespace {
constexpr int kF       = 50;
constexpr int kE       = 64;
constexpr int kD       = 128;
constexpr int kPairs   = 4;                      // b-pairs per CTA (8 b)
constexpr int kGrid    = 16384 / (2 * kPairs);   // 2048 CTAs
constexpr int kThreads = 256;
constexpr uint32_t kBufB = 8192;   // one X tile: 64 f-rows x 128B (64 fp16 e)
}

__device__ __forceinline__ uint32_t smem_u32(const void* p) {
    uint32_t a;
    asm("{ .reg .u64 t; cvta.to.shared.u64 t, %1; cvt.u32.u64 %0, t; }"
        : "=r"(a) : "l"(p));
    return a;
}

__device__ __forceinline__ uint32_t packh2(float lo, float hi) {
    __half2 h = __floats2half2_rn(lo, hi);
    return *reinterpret_cast<uint32_t*>(&h);
}

__device__ __forceinline__ void ldsm4t(uint32_t& r0, uint32_t& r1, uint32_t& r2,
                                       uint32_t& r3, uint32_t a) {
    asm volatile(
        "ldmatrix.sync.aligned.m8n8.x4.trans.shared.b16 {%0,%1,%2,%3}, [%4];"
        : "=r"(r0), "=r"(r1), "=r"(r2), "=r"(r3) : "r"(a));
}

__device__ __forceinline__ void mma16816(float d[4], const uint32_t a[4],
                                         uint32_t b0, uint32_t b1) {
    asm volatile(
        "mma.sync.aligned.m16n8k16.row.col.f32.f16.f16.f32 "
        "{%0,%1,%2,%3}, {%4,%5,%6,%7}, {%8,%9}, {%0,%1,%2,%3};"
        : "+f"(d[0]), "+f"(d[1]), "+f"(d[2]), "+f"(d[3])
        : "r"(a[0]), "r"(a[1]), "r"(a[2]), "r"(a[3]), "r"(b0), "r"(b1));
}

__global__ void __launch_bounds__(kThreads, 3)
InnerProduct_f16_kernel(const float* __restrict__ X,
                        const float* __restrict__ Th,
                        float* __restrict__ out) {
    __shared__ __align__(16) char xs[2 * 2 * kBufB];  // [stage][slot] tiles

    const int tid  = threadIdx.x;
    const int lane = tid & 31;
    const int warp = tid >> 5;
    const int g    = lane >> 2;          // 0..7
    const int q    = lane & 3;           // 0..3
    const int slot  = warp >> 2;         // which b of the pair (0/1)
    const int dbase = (warp & 3) << 5;   // 32 d-rows per warp, full 64 e

    // ---- Theta A-fragments (fp16) in registers, once. 2 m-tiles, 4 k-steps.
    // m16n8k16 A frag: a0:(row g, f 16s+2q,+1)  a1:(row g+8, same f)
    //                  a2:(row g, f 16s+2q+8,+1) a3:(row g+8, same f)
    // K padded 50 -> 64 with zeros (pad products are exactly 0).
    uint32_t af[2][4][4];
#pragma unroll
    for (int t = 0; t < 2; ++t)
#pragma unroll
        for (int s = 0; s < 4; ++s) {
            const int r0 = dbase + 16 * t + g;
            const int r1 = r0 + 8;
            const int f0 = 16 * s + 2 * q;
            const int f1 = f0 + 8;
            auto thv = [&](int d, int f) -> float {
                return (f < kF) ? Th[d * kF + f] : 0.f;
            };
            af[t][s][0] = packh2(thv(r0, f0), thv(r0, f0 + 1));
            af[t][s][1] = packh2(thv(r1, f0), thv(r1, f0 + 1));
            af[t][s][2] = packh2(thv(r0, f1), thv(r0, f1 + 1));
            af[t][s][3] = packh2(thv(r1, f1), thv(r1, f1 + 1));
        }

    const uint32_t sb = smem_u32(xs);
    const size_t bstart = (size_t)blockIdx.x * (2 * kPairs);

    // ---- Zero the f-padding rows (50..63) of all 4 buffers, once.
    // The loader only ever writes f < 50, so they stay zero.
    for (int i = tid; i < 4 * (64 - kF) * 32; i += kThreads) {
        const int buf = i / ((64 - kF) * 32);
        const int r   = i % ((64 - kF) * 32);
        reinterpret_cast<uint32_t*>(xs + buf * kBufB + kF * 128)[r] = 0;
    }

    // ---- Loader (R9-proven): tile stored VERBATIM as [f=64 rows][e=64 fp16],
    // 128B rows, SW128 XOR swizzle on the 16B unit. Task t (0..399):
    // f = t>>3, eb = t&7 -> 2 coalesced LDG.128, pack 4 h2 (adjacent e),
    // 1 swizzled STS.128.
    uint32_t v[2][8];  // packed staging for the 2 tiles of one pair

    auto ldg_cvt = [&](int b, uint32_t* dst) {
        const float* src = X + (bstart + b) * (size_t)(kF * kE);
#pragma unroll
        for (int i = 0; i < 2; ++i) {
            const int t = tid + kThreads * i;
            if (t < 400) {
                const int f  = t >> 3;
                const int eb = t & 7;
                const float4 lo = *reinterpret_cast<const float4*>(
                    src + f * kE + eb * 8);
                const float4 hi = *reinterpret_cast<const float4*>(
                    src + f * kE + eb * 8 + 4);
                dst[i * 4 + 0] = packh2(lo.x, lo.y);
                dst[i * 4 + 1] = packh2(lo.z, lo.w);
                dst[i * 4 + 2] = packh2(hi.x, hi.y);
                dst[i * 4 + 3] = packh2(hi.z, hi.w);
            }
        }
    };
    auto sts_pair = [&](int stage) {
#pragma unroll
        for (int s2 = 0; s2 < 2; ++s2) {
            const uint32_t base =
                sb + (uint32_t)stage * (2 * kBufB) + (uint32_t)s2 * kBufB;
#pragma unroll
            for (int i = 0; i < 2; ++i) {
                const int t = tid + kThreads * i;
                if (t < 400) {
                    const uint32_t f  = (uint32_t)(t >> 3);
                    const uint32_t eb = (uint32_t)(t & 7);
                    const uint32_t off = f * 128u + ((eb ^ (f & 7u)) << 4);
                    asm volatile("st.shared.v4.b32 [%0], {%1,%2,%3,%4};"
                                 :: "r"(base + off), "r"(v[s2][i * 4 + 0]),
                                    "r"(v[s2][i * 4 + 1]), "r"(v[s2][i * 4 + 2]),
                                    "r"(v[s2][i * 4 + 3]) : "memory");
                }
            }
        }
    };

    // ---- ldmatrix.x4.trans lane geometry (R9-proven). Matrix j = lane/8,
    // row r = lane%8:
    //   m0=(f-lo8, e-lo8) m1=(f-hi8, e-lo8) m2=(f-lo8, e-hi8) m3=(f-hi8, e-hi8)
    // Lane address: f = 16s + (j&1)*8 + r, e-unit u = 2*nb + (j>>1),
    // swizzled off = f*128 + ((u ^ r) << 4)   [since f&7 == r].
    const int j   = lane >> 3;
    const int r8  = lane & 7;
    const uint32_t lrow = (uint32_t)(((j & 1) * 8 + r8) * 128);
    const uint32_t lu   = (uint32_t)(j >> 1);

    // ---- Prologue: pair0 staged+stored, pair1 staged ----
    ldg_cvt(0, v[0]);
    ldg_cvt(1, v[1]);
    sts_pair(0);
    ldg_cvt(2, v[0]);
    ldg_cvt(3, v[1]);
    __syncthreads();

#pragma unroll 1
    for (int it = 0; it < kPairs; ++it) {
        const uint32_t base =
            sb + (uint32_t)(it & 1) * (2 * kBufB) + (uint32_t)slot * kBufB;

        // Store next pair (data loaded last iter), prefetch pair after next.
        if (it + 1 < kPairs) sts_pair((it + 1) & 1);
        if (it + 2 < kPairs) {
            ldg_cvt(2 * (it + 2), v[0]);
            ldg_cvt(2 * (it + 2) + 1, v[1]);
        }

        // ---- proj[d,e] = sum_f Theta[d,f]*X[f,e], n-block at a time.
        // Each n-block's accumulators die immediately into the running
        // squared sums -> only 16 live acc regs instead of 64.
        float sum[2][2];
        sum[0][0] = sum[0][1] = sum[1][0] = sum[1][1] = 0.f;

#pragma unroll
        for (int nb = 0; nb < 4; ++nb) {
            float acc[2][2][4];
#pragma unroll
            for (int t = 0; t < 2; ++t)
#pragma unroll
                for (int h = 0; h < 2; ++h)
#pragma unroll
                    for (int c = 0; c < 4; ++c) acc[t][h][c] = 0.f;

            const uint32_t u = 2u * (uint32_t)nb + lu;
            const uint32_t coff = (u ^ (uint32_t)r8) << 4;
#pragma unroll
            for (int s = 0; s < 4; ++s) {
                uint32_t b0, b1, b2, b3;
                ldsm4t(b0, b1, b2, b3, base + 2048u * (uint32_t)s + lrow + coff);
                mma16816(acc[0][0], af[0][s], b0, b1);
                mma16816(acc[0][1], af[0][s], b2, b3);
                mma16816(acc[1][0], af[1][s], b0, b1);
                mma16816(acc[1][1], af[1][s], b2, b3);
            }

            // Square-reduce this n-block. C frag rows: c0,c1 -> row g;
            // c2,c3 -> row g+8 (e-position irrelevant, we sum over e).
#pragma unroll
            for (int t = 0; t < 2; ++t)
#pragma unroll
                for (int h = 0; h < 2; ++h) {
                    sum[t][0] = fmaf(acc[t][h][0], acc[t][h][0], sum[t][0]);
                    sum[t][0] = fmaf(acc[t][h][1], acc[t][h][1], sum[t][0]);
                    sum[t][1] = fmaf(acc[t][h][2], acc[t][h][2], sum[t][1]);
                    sum[t][1] = fmaf(acc[t][h][3], acc[t][h][3], sum[t][1]);
                }
        }

        // ---- Final quad reduction (e spread across the 4 lanes of a quad).
        float* op = out + (bstart + 2 * it + slot) * kD + dbase;
#pragma unroll
        for (int t = 0; t < 2; ++t) {
            float s0 = sum[t][0], s1 = sum[t][1];
            s0 += __shfl_xor_sync(0xffffffffu, s0, 1);
            s0 += __shfl_xor_sync(0xffffffffu, s0, 2);
            s1 += __shfl_xor_sync(0xffffffffu, s1, 1);
            s1 += __shfl_xor_sync(0xffffffffu, s1, 2);
            if (q == 0) {
                op[16 * t + g]     = s0;
                op[16 * t + g + 8] = s1;
            }
        }
        __syncthreads();
    }
}

extern "C" void kernel_launch(void* const* d_in, const int* in_sizes, int n_in,
                              void* d_out, int out_size) {
    const float* X  = (const float*)d_in[0];   // inputs [16384, 50, 64] fp32
    const float* Th = (const float*)d_in[1];   // Theta  [128, 50] fp32
    float* out      = (float*)d_out;           // [16384, 128] fp32
    (void)in_sizes; (void)n_in; (void)out_size;

    InnerProduct_f16_kernel<<<kGrid, kThreads>>>(X, Th, out);
}